// round 8
// baseline (speedup 1.0000x reference)
#include <cuda_runtime.h>

#define BB   4
#define NN   256
#define OBSD 40
#define TT   256
#define DIMG 32
#define HEADG 8
#define ACTD 8

__device__ float g_H1[BB * NN * TT];
__device__ float g_EMBp[2][BB * NN * TT];
__device__ float g_NEp[2][BB * NN * TT];
__device__ float g_sumNH[BB * TT];
__device__ float g_sumHID[BB * TT];

// ---------------------------------------------------------------------------
// 32x64 output tile, 128 threads (8x16), 4x4 micro-tile.
// Double-buffered smem k-tiles of 16 + register-fragment pipeline:
// fragment for k-step s+1 loads from smem under the FFMAs of step s.
// Fragment buffers indexed only by compile-time constants (no dynamic k&1).
// ---------------------------------------------------------------------------
template <class FA, class FB>
__device__ __forceinline__ void mm32x64(FA ldA, FB ldB, int nkt,
                                        float acc[4][4], int tid,
                                        float As[2][16][36], float Bs[2][16][68])
{
    const int ty = tid >> 4, tx = tid & 15;
    {
#pragma unroll
        for (int i = 0; i < 4; ++i) {
            int idx = tid + i * 128;
            As[0][idx & 15][idx >> 4] = ldA(0, idx >> 4, idx & 15);
        }
#pragma unroll
        for (int i = 0; i < 8; ++i) {
            int idx = tid + i * 128;
            Bs[0][idx >> 6][idx & 63] = ldB(0, idx >> 6, idx & 63);
        }
    }
    __syncthreads();
    for (int t = 0; t < nkt; ++t) {
        float ra[4], rb[8];
        if (t + 1 < nkt) {
#pragma unroll
            for (int i = 0; i < 4; ++i) {
                int idx = tid + i * 128;
                ra[i] = ldA(t + 1, idx >> 4, idx & 15);
            }
#pragma unroll
            for (int i = 0; i < 8; ++i) {
                int idx = tid + i * 128;
                rb[i] = ldB(t + 1, idx >> 6, idx & 63);
            }
        }
        const int buf = t & 1;
        // register-fragment pipeline: two named buffers, manual 2-step unroll
        float a0[4], b0[4], a1[4], b1[4];
        *(float4*)a0 = *(const float4*)&As[buf][0][ty * 4];
        *(float4*)b0 = *(const float4*)&Bs[buf][0][tx * 4];
#pragma unroll
        for (int k2 = 0; k2 < 8; ++k2) {
            const int k = k2 * 2;
            // even step: consume (a0,b0), prefetch k+1 into (a1,b1)
            *(float4*)a1 = *(const float4*)&As[buf][k + 1][ty * 4];
            *(float4*)b1 = *(const float4*)&Bs[buf][k + 1][tx * 4];
#pragma unroll
            for (int i = 0; i < 4; ++i)
#pragma unroll
                for (int j = 0; j < 4; ++j)
                    acc[i][j] = fmaf(a0[i], b0[j], acc[i][j]);
            // odd step: consume (a1,b1), prefetch k+2 into (a0,b0)
            if (k2 < 7) {
                *(float4*)a0 = *(const float4*)&As[buf][k + 2][ty * 4];
                *(float4*)b0 = *(const float4*)&Bs[buf][k + 2][tx * 4];
            }
#pragma unroll
            for (int i = 0; i < 4; ++i)
#pragma unroll
                for (int j = 0; j < 4; ++j)
                    acc[i][j] = fmaf(a1[i], b1[j], acc[i][j]);
        }
        if (t + 1 < nkt) {
            const int nb = buf ^ 1;
#pragma unroll
            for (int i = 0; i < 4; ++i) {
                int idx = tid + i * 128;
                As[nb][idx & 15][idx >> 4] = ra[i];
            }
#pragma unroll
            for (int i = 0; i < 8; ++i) {
                int idx = tid + i * 128;
                Bs[nb][idx >> 6][idx & 63] = rb[i];
            }
            __syncthreads();
        }
    }
}

// ---------------------------------------------------------------------------
// P0: H1 = relu(obs @ We1 + be1). grid (32,4) = 128 blocks. Zeroes sums.
// ---------------------------------------------------------------------------
__global__ void __launch_bounds__(128)
h1_kernel(const float* __restrict__ x, const float* __restrict__ We1,
          const float* __restrict__ be1)
{
    if (blockIdx.x == 0 && blockIdx.y == 0) {
        for (int i = threadIdx.x; i < BB * TT; i += 128) {
            g_sumNH[i] = 0.f;
            g_sumHID[i] = 0.f;
        }
    }
    __shared__ float As[2][16][36];
    __shared__ float Bs[2][16][68];
    const int r0 = blockIdx.x * 32;
    const int c0 = blockIdx.y * 64;
    const int tid = threadIdx.x, ty = tid >> 4, tx = tid & 15;

    float acc[4][4] = {};
    mm32x64(
        [&](int kt, int r, int k) {
            int kg = kt * 16 + k;
            int row = r0 + r, b = row >> 8, n = row & 255;
            return (kg < OBSD) ? x[b * ((NN + 1) * OBSD) + n * OBSD + kg] : 0.f;
        },
        [&](int kt, int kk, int c) {
            int kg = kt * 16 + kk;
            return (kg < OBSD) ? We1[kg * TT + c0 + c] : 0.f;
        },
        3, acc, tid, As, Bs);

#pragma unroll
    for (int i = 0; i < 4; ++i)
#pragma unroll
        for (int j = 0; j < 4; ++j) {
            int c = c0 + tx * 4 + j;
            g_H1[(r0 + ty * 4 + i) * TT + c] = fmaxf(acc[i][j] + be1[c], 0.f);
        }
}

// ---------------------------------------------------------------------------
// P1: EMBp[s] = H1 @ We2 over K-half s. grid (32,4,2) = 256 blocks.
// ---------------------------------------------------------------------------
__global__ void __launch_bounds__(128)
emb_kernel(const float* __restrict__ We2)
{
    __shared__ float As[2][16][36];
    __shared__ float Bs[2][16][68];
    const int r0 = blockIdx.x * 32;
    const int c0 = blockIdx.y * 64;
    const int kb = blockIdx.z * 128;
    const int tid = threadIdx.x, ty = tid >> 4, tx = tid & 15;

    float acc[4][4] = {};
    mm32x64(
        [&](int kt, int r, int k) { return g_H1[(r0 + r) * TT + kb + kt * 16 + k]; },
        [&](int kt, int kk, int c) { return We2[(kb + kt * 16 + kk) * TT + c0 + c]; },
        8, acc, tid, As, Bs);

    float* C = &g_EMBp[blockIdx.z][0];
#pragma unroll
    for (int i = 0; i < 4; ++i)
#pragma unroll
        for (int j = 0; j < 4; ++j)
            C[(r0 + ty * 4 + i) * TT + c0 + tx * 4 + j] = acc[i][j];
}

// ---------------------------------------------------------------------------
// P2: NEp[s][b] = adj @ EMB[b] over K-half s; EMB = relu(p0+p1+be2) on load.
// grid (8,4,8) = 256 blocks, z = b*2+s.
// ---------------------------------------------------------------------------
__global__ void __launch_bounds__(128)
ne_kernel(const float* __restrict__ adj, const float* __restrict__ be2)
{
    __shared__ float As[2][16][36];
    __shared__ float Bs[2][16][68];
    const int b = blockIdx.z >> 1;
    const int s = blockIdx.z & 1;
    const int kb = s * 128;
    const int r0 = blockIdx.x * 32;
    const int c0 = blockIdx.y * 64;
    const int ebase = b * (NN * TT);
    const int tid = threadIdx.x, ty = tid >> 4, tx = tid & 15;

    float acc[4][4] = {};
    mm32x64(
        [&](int kt, int r, int k) { return adj[(r0 + r) * NN + kb + kt * 16 + k]; },
        [&](int kt, int kk, int c) {
            int col = c0 + c;
            int ei = ebase + (kb + kt * 16 + kk) * TT + col;
            return fmaxf(g_EMBp[0][ei] + g_EMBp[1][ei] + be2[col], 0.f);
        },
        8, acc, tid, As, Bs);

    float* C = &g_NEp[s][ebase];
#pragma unroll
    for (int i = 0; i < 4; ++i)
#pragma unroll
        for (int j = 0; j < 4; ++j)
            C[(r0 + ty * 4 + i) * TT + c0 + tx * 4 + j] = acc[i][j];
}

// ---------------------------------------------------------------------------
// P3: colsum over rows of relu(NE @ {Wn|Wh} + bias); NE = p0+p1 on load.
// grid (8,8,4) = 256 blocks.
// ---------------------------------------------------------------------------
__global__ void __launch_bounds__(128)
colsum_kernel(const float* __restrict__ Wn, const float* __restrict__ bn,
              const float* __restrict__ Wh, const float* __restrict__ bh)
{
    __shared__ float As[2][16][36];
    __shared__ float Bs[2][16][68];
    const int b = blockIdx.z;
    const int ct = blockIdx.y & 3;
    const int w = blockIdx.y >> 2;
    const int r0 = blockIdx.x * 32;
    const int c0 = ct * 64;
    const int abase = b * (NN * TT);
    const float* W = (w ? Wh : Wn) + c0;
    const int tid = threadIdx.x, ty = tid >> 4, tx = tid & 15;

    float acc[4][4] = {};
    mm32x64(
        [&](int kt, int r, int k) {
            int ai = abase + (r0 + r) * TT + kt * 16 + k;
            return g_NEp[0][ai] + g_NEp[1][ai];
        },
        [&](int kt, int kk, int c) { return W[(kt * 16 + kk) * TT + c]; },
        16, acc, tid, As, Bs);

    const float* bi = (w ? bh : bn);
    float* dst = (w ? g_sumHID : g_sumNH);
    float* red = &As[0][0][0];   // 8*64 floats
    __syncthreads();
#pragma unroll
    for (int j = 0; j < 4; ++j) {
        int col = tx * 4 + j;
        float bv = bi[c0 + col];
        float s = 0.f;
#pragma unroll
        for (int i = 0; i < 4; ++i) s += fmaxf(acc[i][j] + bv, 0.f);
        red[ty * 64 + col] = s;
    }
    __syncthreads();
    if (tid < 64) {
        float s = 0.f;
#pragma unroll
        for (int t2 = 0; t2 < 8; ++t2) s += red[t2 * 64 + tid];
        atomicAdd(&dst[b * TT + c0 + tid], s);
    }
}

// ---------------------------------------------------------------------------
// P4: epilogue per batch.
// ---------------------------------------------------------------------------
__global__ void __launch_bounds__(256)
final_kernel(const float* __restrict__ x, const float* __restrict__ be2,
             const float* __restrict__ Wl, const float* __restrict__ bl,
             const float* __restrict__ Wa, const float* __restrict__ ba,
             float* __restrict__ out)
{
    __shared__ float er[256];
    __shared__ float av[256];
    __shared__ float prod[256];
    __shared__ float mx[8], sm[8];
    __shared__ float od[32];

    const int b = blockIdx.x;
    const int t = threadIdx.x;

    const int tgt = (int)x[b * ((NN + 1) * OBSD) + NN * OBSD];
    int ei = (b * NN + tgt) * TT + t;
    er[t] = fmaxf(g_EMBp[0][ei] + g_EMBp[1][ei] + be2[t], 0.f);
    __syncthreads();

    float acc = bl[t];
#pragma unroll 8
    for (int k = 0; k < TT; ++k) acc = fmaf(er[k], Wl[k * TT + t], acc);
    float l = fmaxf(acc, 0.f);
    av[t] = l * g_sumNH[b * TT + t];
    __syncthreads();

    if (t < HEADG) {
        float m = -1e30f;
        for (int d = 0; d < DIMG; ++d) m = fmaxf(m, av[d * HEADG + t]);
        float s = 0.f;
        for (int d = 0; d < DIMG; ++d) s += __expf(av[d * HEADG + t] - m);
        mx[t] = m; sm[t] = s;
    }
    __syncthreads();

    int h = t & (HEADG - 1);
    float attn = __expf(av[t] - mx[h]) / sm[h];
    prod[t] = attn * g_sumHID[b * TT + t];
    __syncthreads();

    if (t < DIMG) {
        float s = 0.f;
#pragma unroll
        for (int hh = 0; hh < HEADG; ++hh) s += prod[t * HEADG + hh];
        od[t] = s * (1.0f / HEADG);
    }
    __syncthreads();

    if (t < ACTD) {
        float a = ba[t];
#pragma unroll
        for (int d = 0; d < DIMG; ++d) a = fmaf(od[d], Wa[d * ACTD + t], a);
        out[b * ACTD + t] = a;
    }
}

// ---------------------------------------------------------------------------
extern "C" void kernel_launch(void* const* d_in, const int* in_sizes, int n_in,
                              void* d_out, int out_size)
{
    const float* x   = (const float*)d_in[0];
    const float* adj = (const float*)d_in[1];
    const float* We1 = (const float*)d_in[2];
    const float* be1 = (const float*)d_in[3];
    const float* We2 = (const float*)d_in[4];
    const float* be2 = (const float*)d_in[5];
    const float* Wl  = (const float*)d_in[6];
    const float* bl  = (const float*)d_in[7];
    const float* Wn  = (const float*)d_in[8];
    const float* bn  = (const float*)d_in[9];
    const float* Wh  = (const float*)d_in[10];
    const float* bh  = (const float*)d_in[11];
    const float* Wa  = (const float*)d_in[12];
    const float* ba  = (const float*)d_in[13];
    float* out = (float*)d_out;

    h1_kernel<<<dim3(32, 4), 128>>>(x, We1, be1);
    emb_kernel<<<dim3(32, 4, 2), 128>>>(We2);
    ne_kernel<<<dim3(8, 4, 8), 128>>>(adj, be2);
    colsum_kernel<<<dim3(8, 8, 4), 128>>>(Wn, bn, Wh, bh);
    final_kernel<<<BB, 256>>>(x, be2, Wl, bl, Wa, ba, out);
}